// round 15
// baseline (speedup 1.0000x reference)
#include <cuda_runtime.h>
#include <cuda_fp16.h>
#include <math.h>
#include <stdint.h>

// Problem shape (fixed by the dataset): N = M = 4096, D = 256, K = 256.
#define NMAX 4096
#define DK   256
#define KD2  768          // extended K: 3-term fp16 split [ah|ah|al] x [bh|bl|bh]
#define KSTEPS 12         // KD2 / 64
#define KTOP 256
#define CAP  16384

#define SROW 72           // smem row stride in halves (64 + 8 pad, conflict-free)
#define ABUF_HALVES (2 * 128 * SROW)
#define DYN_SMEM (2 * ABUF_HALVES * 2)   // A + B double-buffered, bytes = 73728

// ------------------------- device scratch (no allocs allowed) ---------------
__device__ float g_ms[(size_t)NMAX * NMAX];     // exp(2*dot - 2), row-major [N, M]  (64 MB)
__device__ __half g_A2[(size_t)NMAX * KD2];
__device__ __half g_B2[(size_t)NMAX * KD2];
__device__ float g_rowp[32][NMAX];              // per-column-block row partial sums
__device__ float g_colp[32][NMAX];              // per-row-block col partial sums
__device__ float g_rowinv[NMAX];
__device__ float g_colinv[NMAX];
__device__ unsigned int g_rowmax[NMAX];         // per-row max score (uint bits)
__device__ unsigned int g_hist1[4096];          // histogram of the 4096 rowmax values
__device__ unsigned int g_thresh;
__device__ unsigned int g_candCount;
__device__ unsigned long long g_cand[CAP];

// bit-exact score used identically in rowmax / compact passes
__device__ __forceinline__ float score_val(float ms, float ri, float ci) {
    return __fmul_rn(__fmul_rn(ms, ri), __fmul_rn(ms, ci));
}

__device__ __forceinline__ uint32_t smem_u32(const void* p) {
    uint32_t a;
    asm("{ .reg .u64 t; cvta.to.shared.u64 t, %1; cvt.u32.u64 %0, t; }" : "=r"(a) : "l"(p));
    return a;
}

// ------------------------- split + zero (merged; graph-replay idempotent) ---
__global__ void k_split(const float* __restrict__ A, const float* __restrict__ B) {
    // first 16 blocks zero the mutable selection state (consumed only by later
    // launches in the same stream -> ordering is guaranteed)
    if (blockIdx.x < 16) {
        int z = blockIdx.x * blockDim.x + threadIdx.x;   // 0..4095
        g_hist1[z] = 0;
        if (z == 0) { g_candCount = 0; g_thresh = 0; }
    }

    int idx = blockIdx.x * blockDim.x + threadIdx.x;     // 0 .. 4096*256-1
    int row = idx >> 8;
    int c   = idx & 255;
    size_t base = (size_t)row * KD2;

    float a = A[idx];
    __half ah = __float2half_rn(a);
    __half al = __float2half_rn(a - __half2float(ah));
    g_A2[base + c]        = ah;
    g_A2[base + 256 + c]  = ah;
    g_A2[base + 512 + c]  = al;

    float b = B[idx];
    __half bh = __float2half_rn(b);
    __half bl = __float2half_rn(b - __half2float(bh));
    g_B2[base + c]        = bh;
    g_B2[base + 256 + c]  = bl;
    g_B2[base + 512 + c]  = bh;
}

// ------------------------- HMMA fp16 GEMM + exp + fused partial sums --------
// CTA = 128x128, 256 threads / 8 warps, warp tile 32x64, k-step 64, cp.async.
// (R10/R12 configuration — validated.)
__global__ void __launch_bounds__(256, 2) k_gemm_mma(int M) {
    extern __shared__ __half dyn[];
    __half* Asm = dyn;                    // [2][128][SROW]
    __half* Bsm = dyn + ABUF_HALVES;      // [2][128][SROW]
    __shared__ float sm_colp[4][128];
    __shared__ float sm_rowp[2][4][32];

    const int tid  = threadIdx.x;
    const int lane = tid & 31;
    const int warp = tid >> 5;        // 0..7
    const int wr   = warp >> 1;       // 0..3  (32-row band)
    const int wc   = warp & 1;        // 0..1  (64-col band)
    const int i0   = blockIdx.y * 128;
    const int j0   = blockIdx.x * 128;

    float acc[2][8][4];
#pragma unroll
    for (int a = 0; a < 2; a++)
#pragma unroll
        for (int b = 0; b < 8; b++)
#pragma unroll
            for (int c = 0; c < 4; c++) acc[a][b][c] = 0.0f;

    const __half* Abase = &g_A2[(size_t)i0 * KD2];
    const __half* Bbase = &g_B2[(size_t)j0 * KD2];

    const uint32_t sA = smem_u32(Asm);
    const uint32_t sB = smem_u32(Bsm);

// 1024 16B-chunks per (matrix, buffer); 256 threads -> 4 chunks each.
#define PREFETCH(buf, kc) do {                                                        \
    _Pragma("unroll")                                                                 \
    for (int i = 0; i < 4; i++) {                                                     \
        int idx = tid + 256 * i;                                                      \
        int row = idx >> 3;                                                           \
        int seg = idx & 7;                                                            \
        const void* sa = Abase + (size_t)row * KD2 + (kc) * 64 + seg * 8;             \
        uint32_t da = sA + (((buf) * 128 + row) * SROW + seg * 8) * 2;                \
        asm volatile("cp.async.cg.shared.global [%0], [%1], 16;" :: "r"(da), "l"(sa));\
        const void* sb = Bbase + (size_t)row * KD2 + (kc) * 64 + seg * 8;             \
        uint32_t db = sB + (((buf) * 128 + row) * SROW + seg * 8) * 2;                \
        asm volatile("cp.async.cg.shared.global [%0], [%1], 16;" :: "r"(db), "l"(sb));\
    }                                                                                 \
    asm volatile("cp.async.commit_group;" ::: "memory");                              \
} while (0)

    const int a_row  = wr * 32 + (lane & 15);
    const int a_col  = (lane >> 4) * 8;
    const int b_row  = wc * 64 + (lane >> 4) * 8 + (lane & 7);
    const int b_col  = ((lane >> 3) & 1) * 8;

    PREFETCH(0, 0);

    for (int kc = 0; kc < KSTEPS; kc++) {
        const int cur = kc & 1;
        if (kc + 1 < KSTEPS) {
            PREFETCH(cur ^ 1, kc + 1);
            asm volatile("cp.async.wait_group 1;" ::: "memory");
        } else {
            asm volatile("cp.async.wait_group 0;" ::: "memory");
        }
        __syncthreads();

#pragma unroll
        for (int h = 0; h < 4; h++) {
            uint32_t af[2][4], bfr[4][4];
#pragma unroll
            for (int mi = 0; mi < 2; mi++) {
                uint32_t addr = sA + (((cur * 128 + a_row + mi * 16) * SROW) + a_col + 16 * h) * 2;
                asm volatile("ldmatrix.sync.aligned.m8n8.x4.shared.b16 {%0,%1,%2,%3}, [%4];"
                             : "=r"(af[mi][0]), "=r"(af[mi][1]), "=r"(af[mi][2]), "=r"(af[mi][3])
                             : "r"(addr));
            }
#pragma unroll
            for (int ni = 0; ni < 4; ni++) {
                uint32_t addr = sB + (((cur * 128 + b_row + ni * 16) * SROW) + b_col + 16 * h) * 2;
                asm volatile("ldmatrix.sync.aligned.m8n8.x4.shared.b16 {%0,%1,%2,%3}, [%4];"
                             : "=r"(bfr[ni][0]), "=r"(bfr[ni][1]), "=r"(bfr[ni][2]), "=r"(bfr[ni][3])
                             : "r"(addr));
            }
#pragma unroll
            for (int mi = 0; mi < 2; mi++)
#pragma unroll
                for (int nj = 0; nj < 8; nj++) {
                    const uint32_t bb0 = bfr[nj >> 1][(nj & 1) * 2];
                    const uint32_t bb1 = bfr[nj >> 1][(nj & 1) * 2 + 1];
                    asm volatile(
                        "mma.sync.aligned.m16n8k16.row.col.f32.f16.f16.f32 "
                        "{%0,%1,%2,%3}, {%4,%5,%6,%7}, {%8,%9}, {%0,%1,%2,%3};"
                        : "+f"(acc[mi][nj][0]), "+f"(acc[mi][nj][1]),
                          "+f"(acc[mi][nj][2]), "+f"(acc[mi][nj][3])
                        : "r"(af[mi][0]), "r"(af[mi][1]), "r"(af[mi][2]), "r"(af[mi][3]),
                          "r"(bb0), "r"(bb1));
                }
        }
        __syncthreads();
    }
#undef PREFETCH

    // epilogue: convert acc -> ms in place
#pragma unroll
    for (int mi = 0; mi < 2; mi++)
#pragma unroll
        for (int nj = 0; nj < 8; nj++)
#pragma unroll
            for (int c = 0; c < 4; c++)
                acc[mi][nj][c] = expf(fmaf(2.0f, acc[mi][nj][c], -2.0f));

    const int erow = i0 + wr * 32 + (lane >> 2);
    const int ecol = j0 + wc * 64 + (lane & 3) * 2;

    float rp0 = 0.0f, rp1 = 0.0f, rp2 = 0.0f, rp3 = 0.0f;
#pragma unroll
    for (int nj = 0; nj < 8; nj++) {
        float c0 = acc[0][nj][0] + acc[0][nj][2] + acc[1][nj][0] + acc[1][nj][2];
        float c1 = acc[0][nj][1] + acc[0][nj][3] + acc[1][nj][1] + acc[1][nj][3];
        c0 += __shfl_xor_sync(0xFFFFFFFFu, c0, 4);
        c1 += __shfl_xor_sync(0xFFFFFFFFu, c1, 4);
        c0 += __shfl_xor_sync(0xFFFFFFFFu, c0, 8);
        c1 += __shfl_xor_sync(0xFFFFFFFFu, c1, 8);
        c0 += __shfl_xor_sync(0xFFFFFFFFu, c0, 16);
        c1 += __shfl_xor_sync(0xFFFFFFFFu, c1, 16);
        if (lane < 4) {
            sm_colp[wr][wc * 64 + nj * 8 + lane * 2]     = c0;
            sm_colp[wr][wc * 64 + nj * 8 + lane * 2 + 1] = c1;
        }
        rp0 += acc[0][nj][0] + acc[0][nj][1];
        rp1 += acc[0][nj][2] + acc[0][nj][3];
        rp2 += acc[1][nj][0] + acc[1][nj][1];
        rp3 += acc[1][nj][2] + acc[1][nj][3];
        float2 lo0 = make_float2(acc[0][nj][0], acc[0][nj][1]);
        float2 hi0 = make_float2(acc[0][nj][2], acc[0][nj][3]);
        float2 lo1 = make_float2(acc[1][nj][0], acc[1][nj][1]);
        float2 hi1 = make_float2(acc[1][nj][2], acc[1][nj][3]);
        *(float2*)&g_ms[(size_t)(erow)      * M + ecol + nj * 8] = lo0;
        *(float2*)&g_ms[(size_t)(erow + 8)  * M + ecol + nj * 8] = hi0;
        *(float2*)&g_ms[(size_t)(erow + 16) * M + ecol + nj * 8] = lo1;
        *(float2*)&g_ms[(size_t)(erow + 24) * M + ecol + nj * 8] = hi1;
    }
    rp0 += __shfl_xor_sync(0xFFFFFFFFu, rp0, 1);
    rp1 += __shfl_xor_sync(0xFFFFFFFFu, rp1, 1);
    rp2 += __shfl_xor_sync(0xFFFFFFFFu, rp2, 1);
    rp3 += __shfl_xor_sync(0xFFFFFFFFu, rp3, 1);
    rp0 += __shfl_xor_sync(0xFFFFFFFFu, rp0, 2);
    rp1 += __shfl_xor_sync(0xFFFFFFFFu, rp1, 2);
    rp2 += __shfl_xor_sync(0xFFFFFFFFu, rp2, 2);
    rp3 += __shfl_xor_sync(0xFFFFFFFFu, rp3, 2);
    if ((lane & 3) == 0) {
        int r = lane >> 2;                // 0..7
        sm_rowp[wc][wr][r]      = rp0;
        sm_rowp[wc][wr][r + 8]  = rp1;
        sm_rowp[wc][wr][r + 16] = rp2;
        sm_rowp[wc][wr][r + 24] = rp3;
    }
    __syncthreads();
    if (tid < 128) {
        g_rowp[blockIdx.x][i0 + tid] = sm_rowp[0][tid >> 5][tid & 31] + sm_rowp[1][tid >> 5][tid & 31];
        g_colp[blockIdx.y][j0 + tid] = sm_colp[0][tid] + sm_colp[1][tid] + sm_colp[2][tid] + sm_colp[3][tid];
    }
}

// ------------------------- reduce partials -> inverse sums ------------------
// (validated R12 configuration: 32 blocks x 256 threads)
__global__ void k_sums() {
    int t = blockIdx.x * blockDim.x + threadIdx.x;    // 0..8191
    if (t < 4096) {
        float s = 0.0f;
#pragma unroll
        for (int p = 0; p < 32; p++) s += g_rowp[p][t];
        g_rowinv[t] = 1.0f / s;
    } else {
        int c = t - 4096;
        float s = 0.0f;
#pragma unroll
        for (int p = 0; p < 32; p++) s += g_colp[p][c];
        g_colinv[c] = 1.0f / s;
    }
}

// ------------------------- per-row max (no per-element atomics) -------------
// Also histograms the 4096 rowmax values (1 atomic per row).
__global__ void k_rowmax(int N, int M) {
    __shared__ unsigned int sm_red[8];
    const int i0 = blockIdx.x * 8;
    for (int r = 0; r < 8; r++) {
        const int i = i0 + r;
        const float ri = g_rowinv[i];
        const float4* row = (const float4*)&g_ms[(size_t)i * M];
        const float4* cin = (const float4*)g_colinv;
        unsigned int umax = 0;
        for (int j = threadIdx.x; j < M / 4; j += blockDim.x) {
            float4 ms = row[j];
            float4 ci = cin[j];
            unsigned int u0 = __float_as_uint(score_val(ms.x, ri, ci.x));
            unsigned int u1 = __float_as_uint(score_val(ms.y, ri, ci.y));
            unsigned int u2 = __float_as_uint(score_val(ms.z, ri, ci.z));
            unsigned int u3 = __float_as_uint(score_val(ms.w, ri, ci.w));
            umax = max(umax, max(max(u0, u1), max(u2, u3)));
        }
#pragma unroll
        for (int st = 16; st > 0; st >>= 1)
            umax = max(umax, __shfl_xor_sync(0xFFFFFFFFu, umax, st));
        if ((threadIdx.x & 31) == 0) sm_red[threadIdx.x >> 5] = umax;
        __syncthreads();
        if (threadIdx.x == 0) {
            unsigned int m = sm_red[0];
#pragma unroll
            for (int w = 1; w < 8; w++) m = max(m, sm_red[w]);
            g_rowmax[i] = m;
            atomicAdd(&g_hist1[m >> 20], 1u);
        }
        __syncthreads();
    }
}

// ------------------------- threshold from rowmax order statistics -----------
// T = bin_floor(256th-largest rowmax) <= 256th-largest rowmax <= true top-K
// threshold (the 256 largest rowmaxes ARE 256 distinct matrix elements), so
// {score >= T} is a superset of the exact top-K; k_final rank-sorts exactly.
__global__ void k_findT() {
    __shared__ unsigned int s[256];
    const int t = threadIdx.x;
    unsigned int sum = 0;
    for (int b = t * 16; b < t * 16 + 16; b++) sum += g_hist1[b];
    s[t] = sum;
    __syncthreads();
    if (t == 0) {
        unsigned int cum = 0;
        int chunk = 0;
        for (int c = 255; c >= 0; c--) {
            if (cum + s[c] >= KTOP) { chunk = c; break; }
            cum += s[c];
            if (c == 0) chunk = 0;
        }
        int b;
        for (b = chunk * 16 + 15; b > chunk * 16; b--) {
            unsigned int c2 = g_hist1[b];
            if (cum + c2 >= KTOP) break;
            cum += c2;
        }
        g_thresh = ((unsigned int)b) << 20;
    }
}

// ------------------------- compaction (row-pruned) --------------------------
__global__ void k_compact(int N, int M) {
    const unsigned int T = g_thresh;
    const int i0 = blockIdx.x * 4;
    for (int r = 0; r < 4; r++) {
        const int i = i0 + r;
        if (g_rowmax[i] < T) continue;            // exact: no element in row >= T
        const float ri = g_rowinv[i];
        const float4* row = (const float4*)&g_ms[(size_t)i * M];
        const float4* cin = (const float4*)g_colinv;
        const unsigned int ebase = (unsigned int)i * (unsigned int)M;
        for (int j = threadIdx.x; j < M / 4; j += blockDim.x) {
            float4 ms = row[j];
            float4 ci = cin[j];
            float v[4];
            v[0] = score_val(ms.x, ri, ci.x);
            v[1] = score_val(ms.y, ri, ci.y);
            v[2] = score_val(ms.z, ri, ci.z);
            v[3] = score_val(ms.w, ri, ci.w);
#pragma unroll
            for (int c = 0; c < 4; c++) {
                unsigned int u = __float_as_uint(v[c]);
                if (u >= T) {
                    unsigned int pos = atomicAdd(&g_candCount, 1u);
                    if (pos < CAP) {
                        unsigned int e = ebase + (unsigned int)(j * 4 + c);
                        g_cand[pos] = ((unsigned long long)u << 32)
                                    | (unsigned long long)(0xFFFFFFFFu - e);
                    }
                }
            }
        }
    }
}

// ------------------------- final rank-sort + output (multi-block) -----------
__global__ void k_final(float* __restrict__ out, int M) {
    const int C = (int)min(g_candCount, (unsigned int)CAP);
    const int stride = gridDim.x * blockDim.x;
    for (int c = blockIdx.x * blockDim.x + threadIdx.x; c < C; c += stride) {
        const unsigned long long key = g_cand[c];
        int r = 0;
        for (int o = 0; o < C; o++) r += (g_cand[o] > key);
        if (r < KTOP) {
            unsigned int u   = (unsigned int)(key >> 32);
            unsigned int idx = 0xFFFFFFFFu - (unsigned int)(key & 0xFFFFFFFFu);
            out[r]            = (float)(idx / (unsigned int)M);   // ref index
            out[KTOP + r]     = (float)(idx % (unsigned int)M);   // src index
            out[2 * KTOP + r] = __uint_as_float(u);               // score
        }
    }
}

// ------------------------- launch -------------------------------------------
extern "C" void kernel_launch(void* const* d_in, const int* in_sizes, int n_in,
                              void* d_out, int out_size) {
    const float* ref = (const float*)d_in[0];
    const float* src = (const float*)d_in[1];
    const int D = DK;
    const int N = in_sizes[0] / D;
    const int M = in_sizes[1] / D;
    float* out = (float*)d_out;

    cudaFuncSetAttribute(k_gemm_mma, cudaFuncAttributeMaxDynamicSharedMemorySize, DYN_SMEM);

    k_split<<<(N * D) / 256, 256>>>(ref, src);

    dim3 gg(M / 128, N / 128);
    k_gemm_mma<<<gg, 256, DYN_SMEM>>>(M);

    k_sums<<<32, 256>>>();

    k_rowmax<<<N / 8, 256>>>(N, M);
    k_findT<<<1, 256>>>();
    k_compact<<<N / 4, 256>>>(N, M);
    k_final<<<16, 256>>>(out, M);
}

// round 16
// speedup vs baseline: 1.0767x; 1.0767x over previous
#include <cuda_runtime.h>
#include <cuda_fp16.h>
#include <math.h>
#include <stdint.h>

// Problem shape (fixed by the dataset): N = M = 4096, D = 256, K = 256.
#define NMAX 4096
#define DK   256
#define KD2  768          // extended K: 3-term fp16 split [ah|ah|al] x [bh|bl|bh]
#define KSTEPS 12         // KD2 / 64
#define KTOP 256
#define CAP  16384

#define SROW 72           // smem row stride in halves (64 + 8 pad, conflict-free)
#define ABUF_HALVES (2 * 128 * SROW)
#define DYN_SMEM (2 * ABUF_HALVES * 2)   // A + B double-buffered, bytes = 73728

// ------------------------- device scratch (no allocs allowed) ---------------
__device__ float g_ms[(size_t)NMAX * NMAX];     // exp(2*dot - 2), row-major [N, M]  (64 MB)
__device__ __half g_A2[(size_t)NMAX * KD2];
__device__ __half g_B2[(size_t)NMAX * KD2];
__device__ float g_rowp[32][NMAX];              // per-column-block row partial sums
__device__ float g_colp[32][NMAX];              // per-row-block col partial sums
__device__ float g_rowinv[NMAX];
__device__ float g_colinv[NMAX];
__device__ unsigned int g_rowmax[NMAX];         // per-row max score (uint bits)
__device__ unsigned int g_hist1[4096];          // histogram of the 4096 rowmax values
__device__ unsigned int g_thresh;
__device__ unsigned int g_candCount;
__device__ unsigned long long g_cand[CAP];

// bit-exact score used identically in rowmax / compact passes
__device__ __forceinline__ float score_val(float ms, float ri, float ci) {
    return __fmul_rn(__fmul_rn(ms, ri), __fmul_rn(ms, ci));
}

__device__ __forceinline__ uint32_t smem_u32(const void* p) {
    uint32_t a;
    asm("{ .reg .u64 t; cvta.to.shared.u64 t, %1; cvt.u32.u64 %0, t; }" : "=r"(a) : "l"(p));
    return a;
}

// ------------------------- split + zero (merged; graph-replay idempotent) ---
__global__ void k_split(const float* __restrict__ A, const float* __restrict__ B) {
    // first 16 blocks zero the mutable selection state (consumed only by later
    // launches in the same stream -> ordering is guaranteed)
    if (blockIdx.x < 16) {
        int z = blockIdx.x * blockDim.x + threadIdx.x;   // 0..4095
        g_hist1[z] = 0;
        if (z == 0) { g_candCount = 0; g_thresh = 0; }
    }

    int idx = blockIdx.x * blockDim.x + threadIdx.x;     // 0 .. 4096*256-1
    int row = idx >> 8;
    int c   = idx & 255;
    size_t base = (size_t)row * KD2;

    float a = A[idx];
    __half ah = __float2half_rn(a);
    __half al = __float2half_rn(a - __half2float(ah));
    g_A2[base + c]        = ah;
    g_A2[base + 256 + c]  = ah;
    g_A2[base + 512 + c]  = al;

    float b = B[idx];
    __half bh = __float2half_rn(b);
    __half bl = __float2half_rn(b - __half2float(bh));
    g_B2[base + c]        = bh;
    g_B2[base + 256 + c]  = bl;
    g_B2[base + 512 + c]  = bh;
}

// ------------------------- HMMA fp16 GEMM + exp + fused partial sums --------
// CTA = 128x128, 256 threads / 8 warps, warp tile 32x64, k-step 64, cp.async.
// (R10/R12 configuration — validated.)
__global__ void __launch_bounds__(256, 2) k_gemm_mma(int M) {
    extern __shared__ __half dyn[];
    __half* Asm = dyn;                    // [2][128][SROW]
    __half* Bsm = dyn + ABUF_HALVES;      // [2][128][SROW]
    __shared__ float sm_colp[4][128];
    __shared__ float sm_rowp[2][4][32];

    const int tid  = threadIdx.x;
    const int lane = tid & 31;
    const int warp = tid >> 5;        // 0..7
    const int wr   = warp >> 1;       // 0..3  (32-row band)
    const int wc   = warp & 1;        // 0..1  (64-col band)
    const int i0   = blockIdx.y * 128;
    const int j0   = blockIdx.x * 128;

    float acc[2][8][4];
#pragma unroll
    for (int a = 0; a < 2; a++)
#pragma unroll
        for (int b = 0; b < 8; b++)
#pragma unroll
            for (int c = 0; c < 4; c++) acc[a][b][c] = 0.0f;

    const __half* Abase = &g_A2[(size_t)i0 * KD2];
    const __half* Bbase = &g_B2[(size_t)j0 * KD2];

    const uint32_t sA = smem_u32(Asm);
    const uint32_t sB = smem_u32(Bsm);

// 1024 16B-chunks per (matrix, buffer); 256 threads -> 4 chunks each.
#define PREFETCH(buf, kc) do {                                                        \
    _Pragma("unroll")                                                                 \
    for (int i = 0; i < 4; i++) {                                                     \
        int idx = tid + 256 * i;                                                      \
        int row = idx >> 3;                                                           \
        int seg = idx & 7;                                                            \
        const void* sa = Abase + (size_t)row * KD2 + (kc) * 64 + seg * 8;             \
        uint32_t da = sA + (((buf) * 128 + row) * SROW + seg * 8) * 2;                \
        asm volatile("cp.async.cg.shared.global [%0], [%1], 16;" :: "r"(da), "l"(sa));\
        const void* sb = Bbase + (size_t)row * KD2 + (kc) * 64 + seg * 8;             \
        uint32_t db = sB + (((buf) * 128 + row) * SROW + seg * 8) * 2;                \
        asm volatile("cp.async.cg.shared.global [%0], [%1], 16;" :: "r"(db), "l"(sb));\
    }                                                                                 \
    asm volatile("cp.async.commit_group;" ::: "memory");                              \
} while (0)

    const int a_row  = wr * 32 + (lane & 15);
    const int a_col  = (lane >> 4) * 8;
    const int b_row  = wc * 64 + (lane >> 4) * 8 + (lane & 7);
    const int b_col  = ((lane >> 3) & 1) * 8;

    PREFETCH(0, 0);

    for (int kc = 0; kc < KSTEPS; kc++) {
        const int cur = kc & 1;
        if (kc + 1 < KSTEPS) {
            PREFETCH(cur ^ 1, kc + 1);
            asm volatile("cp.async.wait_group 1;" ::: "memory");
        } else {
            asm volatile("cp.async.wait_group 0;" ::: "memory");
        }
        __syncthreads();

#pragma unroll
        for (int h = 0; h < 4; h++) {
            uint32_t af[2][4], bfr[4][4];
#pragma unroll
            for (int mi = 0; mi < 2; mi++) {
                uint32_t addr = sA + (((cur * 128 + a_row + mi * 16) * SROW) + a_col + 16 * h) * 2;
                asm volatile("ldmatrix.sync.aligned.m8n8.x4.shared.b16 {%0,%1,%2,%3}, [%4];"
                             : "=r"(af[mi][0]), "=r"(af[mi][1]), "=r"(af[mi][2]), "=r"(af[mi][3])
                             : "r"(addr));
            }
#pragma unroll
            for (int ni = 0; ni < 4; ni++) {
                uint32_t addr = sB + (((cur * 128 + b_row + ni * 16) * SROW) + b_col + 16 * h) * 2;
                asm volatile("ldmatrix.sync.aligned.m8n8.x4.shared.b16 {%0,%1,%2,%3}, [%4];"
                             : "=r"(bfr[ni][0]), "=r"(bfr[ni][1]), "=r"(bfr[ni][2]), "=r"(bfr[ni][3])
                             : "r"(addr));
            }
#pragma unroll
            for (int mi = 0; mi < 2; mi++)
#pragma unroll
                for (int nj = 0; nj < 8; nj++) {
                    const uint32_t bb0 = bfr[nj >> 1][(nj & 1) * 2];
                    const uint32_t bb1 = bfr[nj >> 1][(nj & 1) * 2 + 1];
                    asm volatile(
                        "mma.sync.aligned.m16n8k16.row.col.f32.f16.f16.f32 "
                        "{%0,%1,%2,%3}, {%4,%5,%6,%7}, {%8,%9}, {%0,%1,%2,%3};"
                        : "+f"(acc[mi][nj][0]), "+f"(acc[mi][nj][1]),
                          "+f"(acc[mi][nj][2]), "+f"(acc[mi][nj][3])
                        : "r"(af[mi][0]), "r"(af[mi][1]), "r"(af[mi][2]), "r"(af[mi][3]),
                          "r"(bb0), "r"(bb1));
                }
        }
        __syncthreads();
    }
#undef PREFETCH

    // epilogue: convert acc -> ms in place
#pragma unroll
    for (int mi = 0; mi < 2; mi++)
#pragma unroll
        for (int nj = 0; nj < 8; nj++)
#pragma unroll
            for (int c = 0; c < 4; c++)
                acc[mi][nj][c] = expf(fmaf(2.0f, acc[mi][nj][c], -2.0f));

    const int erow = i0 + wr * 32 + (lane >> 2);
    const int ecol = j0 + wc * 64 + (lane & 3) * 2;

    float rp0 = 0.0f, rp1 = 0.0f, rp2 = 0.0f, rp3 = 0.0f;
#pragma unroll
    for (int nj = 0; nj < 8; nj++) {
        float c0 = acc[0][nj][0] + acc[0][nj][2] + acc[1][nj][0] + acc[1][nj][2];
        float c1 = acc[0][nj][1] + acc[0][nj][3] + acc[1][nj][1] + acc[1][nj][3];
        c0 += __shfl_xor_sync(0xFFFFFFFFu, c0, 4);
        c1 += __shfl_xor_sync(0xFFFFFFFFu, c1, 4);
        c0 += __shfl_xor_sync(0xFFFFFFFFu, c0, 8);
        c1 += __shfl_xor_sync(0xFFFFFFFFu, c1, 8);
        c0 += __shfl_xor_sync(0xFFFFFFFFu, c0, 16);
        c1 += __shfl_xor_sync(0xFFFFFFFFu, c1, 16);
        if (lane < 4) {
            sm_colp[wr][wc * 64 + nj * 8 + lane * 2]     = c0;
            sm_colp[wr][wc * 64 + nj * 8 + lane * 2 + 1] = c1;
        }
        rp0 += acc[0][nj][0] + acc[0][nj][1];
        rp1 += acc[0][nj][2] + acc[0][nj][3];
        rp2 += acc[1][nj][0] + acc[1][nj][1];
        rp3 += acc[1][nj][2] + acc[1][nj][3];
        float2 lo0 = make_float2(acc[0][nj][0], acc[0][nj][1]);
        float2 hi0 = make_float2(acc[0][nj][2], acc[0][nj][3]);
        float2 lo1 = make_float2(acc[1][nj][0], acc[1][nj][1]);
        float2 hi1 = make_float2(acc[1][nj][2], acc[1][nj][3]);
        *(float2*)&g_ms[(size_t)(erow)      * M + ecol + nj * 8] = lo0;
        *(float2*)&g_ms[(size_t)(erow + 8)  * M + ecol + nj * 8] = hi0;
        *(float2*)&g_ms[(size_t)(erow + 16) * M + ecol + nj * 8] = lo1;
        *(float2*)&g_ms[(size_t)(erow + 24) * M + ecol + nj * 8] = hi1;
    }
    rp0 += __shfl_xor_sync(0xFFFFFFFFu, rp0, 1);
    rp1 += __shfl_xor_sync(0xFFFFFFFFu, rp1, 1);
    rp2 += __shfl_xor_sync(0xFFFFFFFFu, rp2, 1);
    rp3 += __shfl_xor_sync(0xFFFFFFFFu, rp3, 1);
    rp0 += __shfl_xor_sync(0xFFFFFFFFu, rp0, 2);
    rp1 += __shfl_xor_sync(0xFFFFFFFFu, rp1, 2);
    rp2 += __shfl_xor_sync(0xFFFFFFFFu, rp2, 2);
    rp3 += __shfl_xor_sync(0xFFFFFFFFu, rp3, 2);
    if ((lane & 3) == 0) {
        int r = lane >> 2;                // 0..7
        sm_rowp[wc][wr][r]      = rp0;
        sm_rowp[wc][wr][r + 8]  = rp1;
        sm_rowp[wc][wr][r + 16] = rp2;
        sm_rowp[wc][wr][r + 24] = rp3;
    }
    __syncthreads();
    if (tid < 128) {
        g_rowp[blockIdx.x][i0 + tid] = sm_rowp[0][tid >> 5][tid & 31] + sm_rowp[1][tid >> 5][tid & 31];
        g_colp[blockIdx.y][j0 + tid] = sm_colp[0][tid] + sm_colp[1][tid] + sm_colp[2][tid] + sm_colp[3][tid];
    }
}

// ------------------------- reduce partials -> inverse sums ------------------
// (validated R12 configuration: 32 blocks x 256 threads)
__global__ void k_sums() {
    int t = blockIdx.x * blockDim.x + threadIdx.x;    // 0..8191
    if (t < 4096) {
        float s = 0.0f;
#pragma unroll
        for (int p = 0; p < 32; p++) s += g_rowp[p][t];
        g_rowinv[t] = 1.0f / s;
    } else {
        int c = t - 4096;
        float s = 0.0f;
#pragma unroll
        for (int p = 0; p < 32; p++) s += g_colp[p][c];
        g_colinv[c] = 1.0f / s;
    }
}

// ------------------------- per-row max (one row per block) ------------------
// Same shape as the measured-fast k_rowsum (4096 blocks x 256 threads).
// One global atomic per row feeds the rowmax histogram.
__global__ void k_rowmax(int M) {
    __shared__ unsigned int sm_red[8];
    const int i = blockIdx.x;
    const float ri = g_rowinv[i];
    const float4* row = (const float4*)&g_ms[(size_t)i * M];
    const float4* cin = (const float4*)g_colinv;
    unsigned int umax = 0;
    for (int j = threadIdx.x; j < M / 4; j += blockDim.x) {
        float4 ms = row[j];
        float4 ci = cin[j];
        unsigned int u0 = __float_as_uint(score_val(ms.x, ri, ci.x));
        unsigned int u1 = __float_as_uint(score_val(ms.y, ri, ci.y));
        unsigned int u2 = __float_as_uint(score_val(ms.z, ri, ci.z));
        unsigned int u3 = __float_as_uint(score_val(ms.w, ri, ci.w));
        umax = max(umax, max(max(u0, u1), max(u2, u3)));
    }
#pragma unroll
    for (int st = 16; st > 0; st >>= 1)
        umax = max(umax, __shfl_xor_sync(0xFFFFFFFFu, umax, st));
    if ((threadIdx.x & 31) == 0) sm_red[threadIdx.x >> 5] = umax;
    __syncthreads();
    if (threadIdx.x == 0) {
        unsigned int m = sm_red[0];
#pragma unroll
        for (int w = 1; w < 8; w++) m = max(m, sm_red[w]);
        g_rowmax[i] = m;
        atomicAdd(&g_hist1[m >> 20], 1u);
    }
}

// ------------------------- threshold from rowmax order statistics -----------
// T = bin_floor(256th-largest rowmax) <= 256th-largest rowmax <= true top-K
// threshold (the 256 largest rowmaxes ARE 256 distinct matrix elements), so
// {score >= T} is a superset of the exact top-K; k_final rank-sorts exactly.
__global__ void k_findT() {
    __shared__ unsigned int s[256];
    const int t = threadIdx.x;
    unsigned int sum = 0;
    for (int b = t * 16; b < t * 16 + 16; b++) sum += g_hist1[b];
    s[t] = sum;
    __syncthreads();
    if (t == 0) {
        unsigned int cum = 0;
        int chunk = 0;
        for (int c = 255; c >= 0; c--) {
            if (cum + s[c] >= KTOP) { chunk = c; break; }
            cum += s[c];
            if (c == 0) chunk = 0;
        }
        int b;
        for (b = chunk * 16 + 15; b > chunk * 16; b--) {
            unsigned int c2 = g_hist1[b];
            if (cum + c2 >= KTOP) break;
            cum += c2;
        }
        g_thresh = ((unsigned int)b) << 20;
    }
}

// ------------------------- compaction (row-pruned) --------------------------
__global__ void k_compact(int N, int M) {
    const unsigned int T = g_thresh;
    const int i0 = blockIdx.x * 4;
    for (int r = 0; r < 4; r++) {
        const int i = i0 + r;
        if (g_rowmax[i] < T) continue;            // exact: no element in row >= T
        const float ri = g_rowinv[i];
        const float4* row = (const float4*)&g_ms[(size_t)i * M];
        const float4* cin = (const float4*)g_colinv;
        const unsigned int ebase = (unsigned int)i * (unsigned int)M;
        for (int j = threadIdx.x; j < M / 4; j += blockDim.x) {
            float4 ms = row[j];
            float4 ci = cin[j];
            float v[4];
            v[0] = score_val(ms.x, ri, ci.x);
            v[1] = score_val(ms.y, ri, ci.y);
            v[2] = score_val(ms.z, ri, ci.z);
            v[3] = score_val(ms.w, ri, ci.w);
#pragma unroll
            for (int c = 0; c < 4; c++) {
                unsigned int u = __float_as_uint(v[c]);
                if (u >= T) {
                    unsigned int pos = atomicAdd(&g_candCount, 1u);
                    if (pos < CAP) {
                        unsigned int e = ebase + (unsigned int)(j * 4 + c);
                        g_cand[pos] = ((unsigned long long)u << 32)
                                    | (unsigned long long)(0xFFFFFFFFu - e);
                    }
                }
            }
        }
    }
}

// ------------------------- final rank-sort + output (multi-block) -----------
__global__ void k_final(float* __restrict__ out, int M) {
    const int C = (int)min(g_candCount, (unsigned int)CAP);
    const int stride = gridDim.x * blockDim.x;
    for (int c = blockIdx.x * blockDim.x + threadIdx.x; c < C; c += stride) {
        const unsigned long long key = g_cand[c];
        int r = 0;
        for (int o = 0; o < C; o++) r += (g_cand[o] > key);
        if (r < KTOP) {
            unsigned int u   = (unsigned int)(key >> 32);
            unsigned int idx = 0xFFFFFFFFu - (unsigned int)(key & 0xFFFFFFFFu);
            out[r]            = (float)(idx / (unsigned int)M);   // ref index
            out[KTOP + r]     = (float)(idx % (unsigned int)M);   // src index
            out[2 * KTOP + r] = __uint_as_float(u);               // score
        }
    }
}

// ------------------------- launch -------------------------------------------
extern "C" void kernel_launch(void* const* d_in, const int* in_sizes, int n_in,
                              void* d_out, int out_size) {
    const float* ref = (const float*)d_in[0];
    const float* src = (const float*)d_in[1];
    const int D = DK;
    const int N = in_sizes[0] / D;
    const int M = in_sizes[1] / D;
    float* out = (float*)d_out;

    cudaFuncSetAttribute(k_gemm_mma, cudaFuncAttributeMaxDynamicSharedMemorySize, DYN_SMEM);

    k_split<<<(N * D) / 256, 256>>>(ref, src);

    dim3 gg(M / 128, N / 128);
    k_gemm_mma<<<gg, 256, DYN_SMEM>>>(M);

    k_sums<<<32, 256>>>();

    k_rowmax<<<N, 256>>>(M);
    k_findT<<<1, 256>>>();
    k_compact<<<N / 4, 256>>>(N, M);
    k_final<<<16, 256>>>(out, M);
}